// round 1
// baseline (speedup 1.0000x reference)
#include <cuda_runtime.h>
#include <math.h>

#define FIN 64
#define H   32
#define LAYERS 3
#define MAXN 100000

// ---------------- scratch (__device__ globals; no allocations allowed) ----------------
__device__ float4 g_g [MAXN * 8];   // dinv-scaled input to SpMM      [N,32]
__device__ float4 g_y1[MAXN * 8];   // acc for S h  -> then S h       [N,32]
__device__ float4 g_y2[MAXN * 8];   // acc for S^2 h (raw, scaled in final) [N,32]
__device__ float  g_h [MAXN * H];   // h after input MLP              [N,32]
__device__ float  g_deg [MAXN];
__device__ float  g_dinv[MAXN];

// ---------------- 1: zero accumulators ----------------
__global__ void zero_kernel(int N) {
    int i = blockIdx.x * blockDim.x + threadIdx.x;
    int stride = gridDim.x * blockDim.x;
    float4 z = make_float4(0.f, 0.f, 0.f, 0.f);
    for (int j = i; j < N * 8; j += stride) { g_y1[j] = z; g_y2[j] = z; }
    for (int j = i; j < N;     j += stride) g_deg[j] = 0.f;
}

// ---------------- 2: in-degree ----------------
__global__ void deg_kernel(const int* __restrict__ dst, int E) {
    int i = blockIdx.x * blockDim.x + threadIdx.x;
    int stride = gridDim.x * blockDim.x;
    for (; i < E; i += stride) atomicAdd(&g_deg[dst[i]], 1.0f);
}

// ---------------- 3: D^{-1/2} with clip at 1 ----------------
__global__ void dinv_kernel(int N) {
    int i = blockIdx.x * blockDim.x + threadIdx.x;
    if (i < N) g_dinv[i] = rsqrtf(fmaxf(g_deg[i], 1.0f));
}

// ---------------- 4: input MLP: h = relu(x@W1+b1)@W2+b2 ; g = dinv*h ----------------
__global__ void mlp_kernel(const float* __restrict__ feat,
                           const float* __restrict__ W1, const float* __restrict__ b1,
                           const float* __restrict__ W2, const float* __restrict__ b2,
                           int N) {
    __shared__ float sW1[FIN * H];
    __shared__ float sW2[H * H];
    __shared__ float sb1[H];
    __shared__ float sb2[H];
    int tid = threadIdx.x;
    for (int i = tid; i < FIN * H; i += blockDim.x) sW1[i] = W1[i];
    for (int i = tid; i < H * H;   i += blockDim.x) sW2[i] = W2[i];
    if (tid < H) { sb1[tid] = b1[tid]; sb2[tid] = b2[tid]; }
    __syncthreads();

    int lane = tid & 31;
    int warp = tid >> 5;
    int warpsPerBlock = blockDim.x >> 5;
    int nwarps = warpsPerBlock * gridDim.x;
    float* gflat = (float*)g_g;

    for (int n = blockIdx.x * warpsPerBlock + warp; n < N; n += nwarps) {
        float f0 = feat[n * FIN + lane];
        float f1 = feat[n * FIN + 32 + lane];
        float a = sb1[lane];
        #pragma unroll
        for (int k = 0; k < 32; k++)
            a = fmaf(__shfl_sync(0xffffffffu, f0, k), sW1[k * H + lane], a);
        #pragma unroll
        for (int k = 0; k < 32; k++)
            a = fmaf(__shfl_sync(0xffffffffu, f1, k), sW1[(32 + k) * H + lane], a);
        a = fmaxf(a, 0.f);
        float hv = sb2[lane];
        #pragma unroll
        for (int k = 0; k < 32; k++)
            hv = fmaf(__shfl_sync(0xffffffffu, a, k), sW2[k * H + lane], hv);
        g_h [n * H + lane] = hv;
        gflat[n * H + lane] = hv * g_dinv[n];
    }
}

// ---------------- 5/7: SpMM: acc[dst] += g[src]  (8 threads/edge, float4 + vector red) ----------------
__global__ void spmm_kernel(const int* __restrict__ src, const int* __restrict__ dst,
                            int E, int phase) {
    const float4* __restrict__ gin = g_g;
    float4* acc = (phase == 0) ? g_y1 : g_y2;
    int t = blockIdx.x * blockDim.x + threadIdx.x;
    int total = E * 8;
    int stride = gridDim.x * blockDim.x;
    for (; t < total; t += stride) {
        int e = t >> 3;
        int q = t & 7;
        int s = __ldg(&src[e]);
        int d = __ldg(&dst[e]);
        float4 v = gin[s * 8 + q];
        float4* p = &acc[d * 8 + q];
        asm volatile("red.global.add.v4.f32 [%0], {%1, %2, %3, %4};"
                     :: "l"(p), "f"(v.x), "f"(v.y), "f"(v.z), "f"(v.w) : "memory");
    }
}

// ---------------- 6: y1 = dinv*acc1 ; g = dinv*y1 (input for second SpMM) ----------------
__global__ void scale_kernel(int N) {
    int i = blockIdx.x * blockDim.x + threadIdx.x;
    int total = N * H;
    int stride = gridDim.x * blockDim.x;
    float* y1 = (float*)g_y1;
    float* gf = (float*)g_g;
    for (; i < total; i += stride) {
        float dv = g_dinv[i >> 5];          // H == 32
        float v = y1[i] * dv;
        y1[i] = v;
        gf[i] = v * dv;
    }
}

// ---------------- 8: fused filters + attention + softmax + classifier ----------------
__global__ void final_kernel(const float* __restrict__ W2, const float* __restrict__ b2,
                             const float* __restrict__ Wc, const float* __restrict__ bc,
                             const float* __restrict__ wbern,
                             float* __restrict__ out, int N) {
    __shared__ float sW2[H * H];
    __shared__ float sb2[H];
    __shared__ float sWc[H * 2];
    __shared__ float sbc[2];
    __shared__ float sc[LAYERS][3];
    int tid = threadIdx.x;
    for (int i = tid; i < H * H; i += blockDim.x) sW2[i] = W2[i];
    if (tid < H) {
        sb2[tid] = b2[tid];
        sWc[tid * 2]     = Wc[tid * 2];
        sWc[tid * 2 + 1] = Wc[tid * 2 + 1];
    }
    if (tid < 2) sbc[tid] = bc[tid];
    if (tid < LAYERS) {
        float w0 = fmaxf(wbern[tid * 3 + 0], 0.f);
        float w1 = fmaxf(wbern[tid * 3 + 1], 0.f);
        float w2 = fmaxf(wbern[tid * 3 + 2], 0.f);
        sc[tid][0] = 0.25f * (w0 + 2.f * w1 + w2);
        sc[tid][1] = 0.50f * (w0 - w2);
        sc[tid][2] = 0.25f * (w0 - 2.f * w1 + w2);
    }
    __syncthreads();

    int lane = tid & 31;
    int warp = tid >> 5;
    int warpsPerBlock = blockDim.x >> 5;
    int nwarps = warpsPerBlock * gridDim.x;
    const float* y1 = (const float*)g_y1;
    const float* y2 = (const float*)g_y2;

    for (int n = blockIdx.x * warpsPerBlock + warp; n < N; n += nwarps) {
        float dv  = g_dinv[n];
        float hn  = g_h[n * H + lane];
        float a1  = y1[n * H + lane];          // already fully scaled = S h
        float a2  = y2[n * H + lane] * dv;     // finish scaling = S^2 h

        float f0 = sc[0][0] * hn + sc[0][1] * a1 + sc[0][2] * a2;
        float f1 = sc[1][0] * hn + sc[1][1] * a1 + sc[1][2] * a2;
        float f2 = sc[2][0] * hn + sc[2][1] * a1 + sc[2][2] * a2;

        float px = sb2[lane], p0 = sb2[lane], p1 = sb2[lane], p2 = sb2[lane];
        #pragma unroll
        for (int k = 0; k < 32; k++) {
            float w = sW2[k * H + lane];
            px = fmaf(__shfl_sync(0xffffffffu, hn, k), w, px);
            p0 = fmaf(__shfl_sync(0xffffffffu, f0, k), w, p0);
            p1 = fmaf(__shfl_sync(0xffffffffu, f1, k), w, p1);
            p2 = fmaf(__shfl_sync(0xffffffffu, f2, k), w, p2);
        }
        px = tanhf(px); p0 = tanhf(p0); p1 = tanhf(p1); p2 = tanhf(p2);

        float l0 = p0 * px, l1 = p1 * px, l2 = p2 * px;
        #pragma unroll
        for (int o = 16; o; o >>= 1) {
            l0 += __shfl_xor_sync(0xffffffffu, l0, o);
            l1 += __shfl_xor_sync(0xffffffffu, l1, o);
            l2 += __shfl_xor_sync(0xffffffffu, l2, o);
        }
        float m  = fmaxf(l0, fmaxf(l1, l2));
        float e0 = expf(l0 - m), e1 = expf(l1 - m), e2 = expf(l2 - m);
        float inv = 1.f / (e0 + e1 + e2);
        float res = (e0 * f0 + e1 * f1 + e2 * f2) * inv;

        float o0 = res * sWc[lane * 2];
        float o1 = res * sWc[lane * 2 + 1];
        #pragma unroll
        for (int o = 16; o; o >>= 1) {
            o0 += __shfl_xor_sync(0xffffffffu, o0, o);
            o1 += __shfl_xor_sync(0xffffffffu, o1, o);
        }
        if (lane == 0) {
            out[n * 2]     = o0 + sbc[0];
            out[n * 2 + 1] = o1 + sbc[1];
        }
    }
}

// ---------------- launcher ----------------
extern "C" void kernel_launch(void* const* d_in, const int* in_sizes, int n_in,
                              void* d_out, int out_size) {
    const float* feature = (const float*)d_in[0];
    const float* W1      = (const float*)d_in[1];
    const float* b1      = (const float*)d_in[2];
    const float* W2      = (const float*)d_in[3];
    const float* b2      = (const float*)d_in[4];
    const float* Wc      = (const float*)d_in[5];
    const float* bc      = (const float*)d_in[6];
    const float* wbern   = (const float*)d_in[7];
    const int*   src     = (const int*)d_in[8];
    const int*   dst     = (const int*)d_in[9];

    int N = in_sizes[0] / FIN;
    int E = in_sizes[8];
    float* out = (float*)d_out;

    const int T = 256;
    zero_kernel<<<(N * 8 + T - 1) / T, T>>>(N);
    deg_kernel<<<(E + T - 1) / T, T>>>(dst, E);
    dinv_kernel<<<(N + T - 1) / T, T>>>(N);
    mlp_kernel<<<(N + 7) / 8, T>>>(feature, W1, b1, W2, b2, N);
    spmm_kernel<<<(E * 8 + T - 1) / T, T>>>(src, dst, E, 0);
    scale_kernel<<<(N * H + T - 1) / T, T>>>(N);
    spmm_kernel<<<(E * 8 + T - 1) / T, T>>>(src, dst, E, 1);
    final_kernel<<<(N + 7) / 8, T>>>(W2, b2, Wc, bc, wbern, out, N);
}

// round 2
// speedup vs baseline: 1.0999x; 1.0999x over previous
#include <cuda_runtime.h>
#include <math.h>

#define FIN 64
#define H   32
#define LAYERS 3
#define MAXN 100000
#define MAXE 1700000

// ---------------- scratch ----------------
__device__ float g_g  [MAXN * H];   // h * dinv            (input to spmm1)
__device__ float g_gb [MAXN * H];   // (S h) * dinv        (input to spmm2)
__device__ float g_y1 [MAXN * H];   // S h
__device__ float g_y2 [MAXN * H];   // S^2 h
__device__ float g_h  [MAXN * H];   // h
__device__ float g_dinv[MAXN];
__device__ int   g_degi[MAXN];
__device__ int   g_rowptr[MAXN];
__device__ int   g_cursor[MAXN];
__device__ int   g_bsum[512];
__device__ int   g_boff[512];
__device__ int   g_csrc[MAXE];

// ---------------- zero deg ----------------
__global__ void zero_deg(int N) {
    int i = blockIdx.x * blockDim.x + threadIdx.x;
    if (i < N) g_degi[i] = 0;
}

// ---------------- in-degree (int) ----------------
__global__ void deg_kernel(const int* __restrict__ dst, int E) {
    int i = blockIdx.x * blockDim.x + threadIdx.x;
    if (i < E) atomicAdd(&g_degi[dst[i]], 1);
}

// ---------------- D^{-1/2}, clip 1 ----------------
__global__ void dinv_kernel(int N) {
    int i = blockIdx.x * blockDim.x + threadIdx.x;
    if (i < N) g_dinv[i] = rsqrtf(fmaxf((float)g_degi[i], 1.0f));
}

// ---------------- scan (3-stage exclusive) ----------------
__global__ void scan1(int N) {
    __shared__ int s[256];
    int b = blockIdx.x, tid = threadIdx.x;
    int i = b * 256 + tid;
    int v = (i < N) ? g_degi[i] : 0;
    s[tid] = v;
    __syncthreads();
    #pragma unroll
    for (int o = 1; o < 256; o <<= 1) {
        int t = (tid >= o) ? s[tid - o] : 0;
        __syncthreads();
        s[tid] += t;
        __syncthreads();
    }
    if (i < N) g_rowptr[i] = s[tid] - v;
    if (tid == 255) g_bsum[b] = s[255];
}
__global__ void scan2(int nblk) {
    __shared__ int s[512];
    int tid = threadIdx.x;
    int v = (tid < nblk) ? g_bsum[tid] : 0;
    s[tid] = v;
    __syncthreads();
    #pragma unroll
    for (int o = 1; o < 512; o <<= 1) {
        int t = (tid >= o) ? s[tid - o] : 0;
        __syncthreads();
        s[tid] += t;
        __syncthreads();
    }
    if (tid < nblk) g_boff[tid] = s[tid] - v;
}
__global__ void scan3(int N) {
    int i = blockIdx.x * blockDim.x + threadIdx.x;
    if (i < N) {
        int r = g_rowptr[i] + g_boff[blockIdx.x];
        g_rowptr[i] = r;
        g_cursor[i] = r;
    }
}

// ---------------- scatter edges into CSR ----------------
__global__ void scatter_kernel(const int* __restrict__ src, const int* __restrict__ dst, int E) {
    int i = blockIdx.x * blockDim.x + threadIdx.x;
    if (i < E) {
        int p = atomicAdd(&g_cursor[dst[i]], 1);
        g_csrc[p] = src[i];
    }
}

// ---------------- MLP: thread-per-node ----------------
__global__ void mlp_kernel(const float* __restrict__ feat,
                           const float* __restrict__ W1, const float* __restrict__ b1,
                           const float* __restrict__ W2, const float* __restrict__ b2,
                           int N) {
    __shared__ float sW1[FIN * H];
    __shared__ float sW2[H * H];
    __shared__ float sb1[H];
    __shared__ float sb2[H];
    __shared__ float st[128 * 33];       // transpose staging
    int tid = threadIdx.x;
    for (int i = tid; i < FIN * H; i += blockDim.x) sW1[i] = W1[i];
    for (int i = tid; i < H * H;   i += blockDim.x) sW2[i] = W2[i];
    if (tid < H) { sb1[tid] = b1[tid]; sb2[tid] = b2[tid]; }
    __syncthreads();

    int n = blockIdx.x * 128 + tid;
    bool active = (n < N);

    float acc[H];
    #pragma unroll
    for (int j = 0; j < H; j++) acc[j] = sb1[j];

    const float4* frow = (const float4*)(feat + (size_t)(active ? n : 0) * FIN);
    #pragma unroll 2
    for (int c = 0; c < FIN / 4; c++) {
        float4 f = active ? frow[c] : make_float4(0.f, 0.f, 0.f, 0.f);
        int k = c * 4;
        #pragma unroll
        for (int j = 0; j < H; j += 4) {
            float4 w0 = *(const float4*)&sW1[(k + 0) * H + j];
            float4 w1 = *(const float4*)&sW1[(k + 1) * H + j];
            float4 w2 = *(const float4*)&sW1[(k + 2) * H + j];
            float4 w3 = *(const float4*)&sW1[(k + 3) * H + j];
            acc[j + 0] = fmaf(f.x, w0.x, fmaf(f.y, w1.x, fmaf(f.z, w2.x, fmaf(f.w, w3.x, acc[j + 0]))));
            acc[j + 1] = fmaf(f.x, w0.y, fmaf(f.y, w1.y, fmaf(f.z, w2.y, fmaf(f.w, w3.y, acc[j + 1]))));
            acc[j + 2] = fmaf(f.x, w0.z, fmaf(f.y, w1.z, fmaf(f.z, w2.z, fmaf(f.w, w3.z, acc[j + 2]))));
            acc[j + 3] = fmaf(f.x, w0.w, fmaf(f.y, w1.w, fmaf(f.z, w2.w, fmaf(f.w, w3.w, acc[j + 3]))));
        }
    }
    #pragma unroll
    for (int j = 0; j < H; j++) acc[j] = fmaxf(acc[j], 0.f);

    float hv[H];
    #pragma unroll
    for (int j = 0; j < H; j++) hv[j] = sb2[j];
    #pragma unroll 2
    for (int k = 0; k < H; k += 4) {
        float a0 = acc[k], a1 = acc[k + 1], a2 = acc[k + 2], a3 = acc[k + 3];
        #pragma unroll
        for (int j = 0; j < H; j += 4) {
            float4 w0 = *(const float4*)&sW2[(k + 0) * H + j];
            float4 w1 = *(const float4*)&sW2[(k + 1) * H + j];
            float4 w2 = *(const float4*)&sW2[(k + 2) * H + j];
            float4 w3 = *(const float4*)&sW2[(k + 3) * H + j];
            hv[j + 0] = fmaf(a0, w0.x, fmaf(a1, w1.x, fmaf(a2, w2.x, fmaf(a3, w3.x, hv[j + 0]))));
            hv[j + 1] = fmaf(a0, w0.y, fmaf(a1, w1.y, fmaf(a2, w2.y, fmaf(a3, w3.y, hv[j + 1]))));
            hv[j + 2] = fmaf(a0, w0.z, fmaf(a1, w1.z, fmaf(a2, w2.z, fmaf(a3, w3.z, hv[j + 2]))));
            hv[j + 3] = fmaf(a0, w0.w, fmaf(a1, w1.w, fmaf(a2, w2.w, fmaf(a3, w3.w, hv[j + 3]))));
        }
    }

    // transpose via smem, then coalesced stores of h and g = h*dinv
    #pragma unroll
    for (int j = 0; j < H; j++) st[tid * 33 + j] = hv[j];
    __syncthreads();
    int base = blockIdx.x * 128 * H;
    #pragma unroll
    for (int it = 0; it < 32; it++) {
        int i = it * 128 + tid;
        int nn = i >> 5, jj = i & 31;
        int gn = blockIdx.x * 128 + nn;
        if (gn < N) {
            float v = st[nn * 33 + jj];
            g_h[base + i] = v;
            g_g[base + i] = v * g_dinv[gn];
        }
    }
}

// ---------------- pull SpMM: warp per row, no atomics ----------------
__global__ void spmm_pull(const float* __restrict__ in, float* __restrict__ out,
                          float* __restrict__ out2, int N) {
    int w = (blockIdx.x * blockDim.x + threadIdx.x) >> 5;
    int lane = threadIdx.x & 31;
    if (w >= N) return;
    int start = g_rowptr[w];
    int cnt = g_degi[w];
    const int* cs = g_csrc + start;
    float acc = 0.f;
    int j = 0;
    for (; j + 4 <= cnt; j += 4) {
        int s0 = __ldg(cs + j);
        int s1 = __ldg(cs + j + 1);
        int s2 = __ldg(cs + j + 2);
        int s3 = __ldg(cs + j + 3);
        float v0 = in[s0 * H + lane];
        float v1 = in[s1 * H + lane];
        float v2 = in[s2 * H + lane];
        float v3 = in[s3 * H + lane];
        acc += (v0 + v1) + (v2 + v3);
    }
    for (; j < cnt; j++) acc += in[__ldg(cs + j) * H + lane];
    float dv = g_dinv[w];
    float sv = acc * dv;
    out[w * H + lane] = sv;
    if (out2) out2[w * H + lane] = sv * dv;
}

// ---------------- fused filters + attention + softmax + classifier ----------------
__global__ void final_kernel(const float* __restrict__ W2, const float* __restrict__ b2,
                             const float* __restrict__ Wc, const float* __restrict__ bc,
                             const float* __restrict__ wbern,
                             float* __restrict__ out, int N) {
    __shared__ float sW2[H * H];
    __shared__ float sb2[H];
    __shared__ float sWc[H * 2];
    __shared__ float sbc[2];
    __shared__ float sc[LAYERS][3];
    int tid = threadIdx.x;
    for (int i = tid; i < H * H; i += blockDim.x) sW2[i] = W2[i];
    if (tid < H) {
        sb2[tid] = b2[tid];
        sWc[tid * 2]     = Wc[tid * 2];
        sWc[tid * 2 + 1] = Wc[tid * 2 + 1];
    }
    if (tid < 2) sbc[tid] = bc[tid];
    if (tid < LAYERS) {
        float w0 = fmaxf(wbern[tid * 3 + 0], 0.f);
        float w1 = fmaxf(wbern[tid * 3 + 1], 0.f);
        float w2 = fmaxf(wbern[tid * 3 + 2], 0.f);
        sc[tid][0] = 0.25f * (w0 + 2.f * w1 + w2);
        sc[tid][1] = 0.50f * (w0 - w2);
        sc[tid][2] = 0.25f * (w0 - 2.f * w1 + w2);
    }
    __syncthreads();

    int lane = tid & 31;
    int warp = tid >> 5;
    int warpsPerBlock = blockDim.x >> 5;
    int nwarps = warpsPerBlock * gridDim.x;

    for (int n = blockIdx.x * warpsPerBlock + warp; n < N; n += nwarps) {
        float hn = g_h [n * H + lane];
        float a1 = g_y1[n * H + lane];   // S h     (fully scaled)
        float a2 = g_y2[n * H + lane];   // S^2 h   (fully scaled)

        float f0 = sc[0][0] * hn + sc[0][1] * a1 + sc[0][2] * a2;
        float f1 = sc[1][0] * hn + sc[1][1] * a1 + sc[1][2] * a2;
        float f2 = sc[2][0] * hn + sc[2][1] * a1 + sc[2][2] * a2;

        float px = sb2[lane], p0 = sb2[lane], p1 = sb2[lane], p2 = sb2[lane];
        #pragma unroll
        for (int k = 0; k < 32; k++) {
            float w = sW2[k * H + lane];
            px = fmaf(__shfl_sync(0xffffffffu, hn, k), w, px);
            p0 = fmaf(__shfl_sync(0xffffffffu, f0, k), w, p0);
            p1 = fmaf(__shfl_sync(0xffffffffu, f1, k), w, p1);
            p2 = fmaf(__shfl_sync(0xffffffffu, f2, k), w, p2);
        }
        px = tanhf(px); p0 = tanhf(p0); p1 = tanhf(p1); p2 = tanhf(p2);

        float l0 = p0 * px, l1 = p1 * px, l2 = p2 * px;
        #pragma unroll
        for (int o = 16; o; o >>= 1) {
            l0 += __shfl_xor_sync(0xffffffffu, l0, o);
            l1 += __shfl_xor_sync(0xffffffffu, l1, o);
            l2 += __shfl_xor_sync(0xffffffffu, l2, o);
        }
        float m  = fmaxf(l0, fmaxf(l1, l2));
        float e0 = expf(l0 - m), e1 = expf(l1 - m), e2 = expf(l2 - m);
        float inv = 1.f / (e0 + e1 + e2);
        float res = (e0 * f0 + e1 * f1 + e2 * f2) * inv;

        float o0 = res * sWc[lane * 2];
        float o1 = res * sWc[lane * 2 + 1];
        #pragma unroll
        for (int o = 16; o; o >>= 1) {
            o0 += __shfl_xor_sync(0xffffffffu, o0, o);
            o1 += __shfl_xor_sync(0xffffffffu, o1, o);
        }
        if (lane == 0) {
            out[n * 2]     = o0 + sbc[0];
            out[n * 2 + 1] = o1 + sbc[1];
        }
    }
}

// ---------------- launcher ----------------
extern "C" void kernel_launch(void* const* d_in, const int* in_sizes, int n_in,
                              void* d_out, int out_size) {
    const float* feature = (const float*)d_in[0];
    const float* W1      = (const float*)d_in[1];
    const float* b1      = (const float*)d_in[2];
    const float* W2      = (const float*)d_in[3];
    const float* b2      = (const float*)d_in[4];
    const float* Wc      = (const float*)d_in[5];
    const float* bc      = (const float*)d_in[6];
    const float* wbern   = (const float*)d_in[7];
    const int*   src     = (const int*)d_in[8];
    const int*   dst     = (const int*)d_in[9];

    int N = in_sizes[0] / FIN;
    int E = in_sizes[8];
    float* out = (float*)d_out;

    const int T = 256;
    int nblk = (N + 255) / 256;

    zero_deg<<<nblk, T>>>(N);
    deg_kernel<<<(E + T - 1) / T, T>>>(dst, E);
    dinv_kernel<<<nblk, T>>>(N);
    scan1<<<nblk, 256>>>(N);
    scan2<<<1, 512>>>(nblk);
    scan3<<<nblk, 256>>>(N);
    scatter_kernel<<<(E + T - 1) / T, T>>>(src, dst, E);

    float* gg  = nullptr; float* ggb = nullptr; float* gy1 = nullptr; float* gy2 = nullptr;
    cudaGetSymbolAddress((void**)&gg,  g_g);
    cudaGetSymbolAddress((void**)&ggb, g_gb);
    cudaGetSymbolAddress((void**)&gy1, g_y1);
    cudaGetSymbolAddress((void**)&gy2, g_y2);

    mlp_kernel<<<(N + 127) / 128, 128>>>(feature, W1, b1, W2, b2, N);
    spmm_pull<<<(N + 7) / 8, T>>>(gg,  gy1, ggb, N);     // y1 = S h, gb = dinv*y1
    spmm_pull<<<(N + 7) / 8, T>>>(ggb, gy2, nullptr, N); // y2 = S^2 h
    final_kernel<<<(N + 7) / 8, T>>>(W2, b2, Wc, bc, wbern, out, N);
}

// round 6
// speedup vs baseline: 1.2656x; 1.1507x over previous
#include <cuda_runtime.h>
#include <math.h>

#define FIN 64
#define H   32
#define MAXN 100000
#define MAXE 1700000

// ---------------- scratch ----------------
__device__ float4 g_g4 [MAXN * 8];   // h * dinv              (input to spmm1)
__device__ float4 g_gb4[MAXN * 8];   // (S h) * dinv          (input to spmm2)
__device__ float4 g_y14[MAXN * 8];   // S h (fully scaled)
__device__ float  g_h  [MAXN * H];   // h
__device__ float  g_dinv[MAXN];
__device__ int    g_degi[MAXN];      // INVARIANT: zero at kernel_launch entry
__device__ int    g_rowptr[MAXN];
__device__ int    g_cursor[MAXN];
__device__ int    g_bsum[1024];
__device__ int    g_boff[1024];
__device__ int    g_csrc[MAXE];

// ---------------- in-degree (degi pre-zeroed invariant) ----------------
__global__ void deg_kernel(const int* __restrict__ dst, int E) {
    int i = blockIdx.x * blockDim.x + threadIdx.x;
    if (i < E) atomicAdd(&g_degi[dst[i]], 1);
}

// ---------------- scan1: per-block exclusive scan of degi + dinv ----------------
__global__ void __launch_bounds__(512) scan1(int N) {
    __shared__ int wsum[16];
    int tid = threadIdx.x, lane = tid & 31, wid = tid >> 5;
    int i = blockIdx.x * 512 + tid;
    int v = (i < N) ? g_degi[i] : 0;
    int x = v;
    #pragma unroll
    for (int o = 1; o < 32; o <<= 1) {
        int t = __shfl_up_sync(0xffffffffu, x, o);
        if (lane >= o) x += t;
    }
    if (lane == 31) wsum[wid] = x;
    __syncthreads();
    if (tid < 16) {
        int y = wsum[tid];
        #pragma unroll
        for (int o = 1; o < 16; o <<= 1) {
            int t = __shfl_up_sync(0xffffu, y, o);
            if (tid >= o) y += t;
        }
        wsum[tid] = y;
    }
    __syncthreads();
    int incl = x + (wid ? wsum[wid - 1] : 0);
    if (i < N) {
        g_rowptr[i] = incl - v;
        g_dinv[i]   = rsqrtf(fmaxf((float)v, 1.0f));
    }
    if (tid == 511) g_bsum[blockIdx.x] = incl;
}

// ---------------- scan2: exclusive scan of block sums (single block) ----------------
__global__ void __launch_bounds__(512) scan2(int nblk) {
    __shared__ int wsum[16];
    int tid = threadIdx.x, lane = tid & 31, wid = tid >> 5;
    int v = (tid < nblk) ? g_bsum[tid] : 0;
    int x = v;
    #pragma unroll
    for (int o = 1; o < 32; o <<= 1) {
        int t = __shfl_up_sync(0xffffffffu, x, o);
        if (lane >= o) x += t;
    }
    if (lane == 31) wsum[wid] = x;
    __syncthreads();
    if (tid < 16) {
        int y = wsum[tid];
        #pragma unroll
        for (int o = 1; o < 16; o <<= 1) {
            int t = __shfl_up_sync(0xffffu, y, o);
            if (tid >= o) y += t;
        }
        wsum[tid] = y;
    }
    __syncthreads();
    int off = wid ? wsum[wid - 1] : 0;
    if (tid < nblk) g_boff[tid] = x + off - v;
}

// ---------------- scan3: add block offsets, init cursor ----------------
__global__ void __launch_bounds__(512) scan3(int N) {
    int i = blockIdx.x * 512 + threadIdx.x;
    if (i < N) {
        int r = g_rowptr[i] + g_boff[blockIdx.x];
        g_rowptr[i] = r;
        g_cursor[i] = r;
    }
}

// ---------------- scatter edges into CSR ----------------
__global__ void scatter_kernel(const int* __restrict__ src, const int* __restrict__ dst, int E) {
    int i = blockIdx.x * blockDim.x + threadIdx.x;
    if (i < E) {
        int p = atomicAdd(&g_cursor[dst[i]], 1);
        g_csrc[p] = src[i];
    }
}

// ---------------- MLP: thread-per-node ----------------
__global__ void mlp_kernel(const float* __restrict__ feat,
                           const float* __restrict__ W1, const float* __restrict__ b1,
                           const float* __restrict__ W2, const float* __restrict__ b2,
                           int N) {
    __shared__ __align__(16) float sW1[FIN * H];
    __shared__ __align__(16) float sW2[H * H];
    __shared__ float sb1[H];
    __shared__ float sb2[H];
    __shared__ float st[128 * 33];
    int tid = threadIdx.x;
    for (int i = tid; i < FIN * H; i += blockDim.x) sW1[i] = W1[i];
    for (int i = tid; i < H * H;   i += blockDim.x) sW2[i] = W2[i];
    if (tid < H) { sb1[tid] = b1[tid]; sb2[tid] = b2[tid]; }
    __syncthreads();

    int n = blockIdx.x * 128 + tid;
    bool active = (n < N);

    float acc[H];
    #pragma unroll
    for (int j = 0; j < H; j++) acc[j] = sb1[j];

    const float4* frow = (const float4*)(feat + (size_t)(active ? n : 0) * FIN);
    #pragma unroll 2
    for (int c = 0; c < FIN / 4; c++) {
        float4 f = active ? frow[c] : make_float4(0.f, 0.f, 0.f, 0.f);
        int k = c * 4;
        #pragma unroll
        for (int j = 0; j < H; j += 4) {
            float4 w0 = *(const float4*)&sW1[(k + 0) * H + j];
            float4 w1 = *(const float4*)&sW1[(k + 1) * H + j];
            float4 w2 = *(const float4*)&sW1[(k + 2) * H + j];
            float4 w3 = *(const float4*)&sW1[(k + 3) * H + j];
            acc[j + 0] = fmaf(f.x, w0.x, fmaf(f.y, w1.x, fmaf(f.z, w2.x, fmaf(f.w, w3.x, acc[j + 0]))));
            acc[j + 1] = fmaf(f.x, w0.y, fmaf(f.y, w1.y, fmaf(f.z, w2.y, fmaf(f.w, w3.y, acc[j + 1]))));
            acc[j + 2] = fmaf(f.x, w0.z, fmaf(f.y, w1.z, fmaf(f.z, w2.z, fmaf(f.w, w3.z, acc[j + 2]))));
            acc[j + 3] = fmaf(f.x, w0.w, fmaf(f.y, w1.w, fmaf(f.z, w2.w, fmaf(f.w, w3.w, acc[j + 3]))));
        }
    }
    #pragma unroll
    for (int j = 0; j < H; j++) acc[j] = fmaxf(acc[j], 0.f);

    float hv[H];
    #pragma unroll
    for (int j = 0; j < H; j++) hv[j] = sb2[j];
    #pragma unroll 2
    for (int k = 0; k < H; k += 4) {
        float a0 = acc[k], a1 = acc[k + 1], a2 = acc[k + 2], a3 = acc[k + 3];
        #pragma unroll
        for (int j = 0; j < H; j += 4) {
            float4 w0 = *(const float4*)&sW2[(k + 0) * H + j];
            float4 w1 = *(const float4*)&sW2[(k + 1) * H + j];
            float4 w2 = *(const float4*)&sW2[(k + 2) * H + j];
            float4 w3 = *(const float4*)&sW2[(k + 3) * H + j];
            hv[j + 0] = fmaf(a0, w0.x, fmaf(a1, w1.x, fmaf(a2, w2.x, fmaf(a3, w3.x, hv[j + 0]))));
            hv[j + 1] = fmaf(a0, w0.y, fmaf(a1, w1.y, fmaf(a2, w2.y, fmaf(a3, w3.y, hv[j + 1]))));
            hv[j + 2] = fmaf(a0, w0.z, fmaf(a1, w1.z, fmaf(a2, w2.z, fmaf(a3, w3.z, hv[j + 2]))));
            hv[j + 3] = fmaf(a0, w0.w, fmaf(a1, w1.w, fmaf(a2, w2.w, fmaf(a3, w3.w, hv[j + 3]))));
        }
    }

    #pragma unroll
    for (int j = 0; j < H; j++) st[tid * 33 + j] = hv[j];
    __syncthreads();
    int base = blockIdx.x * 128 * H;
    float* gflat = (float*)g_g4;
    #pragma unroll
    for (int it = 0; it < 32; it++) {
        int i = it * 128 + tid;
        int nn = i >> 5, jj = i & 31;
        int gn = blockIdx.x * 128 + nn;
        if (gn < N) {
            float v = st[nn * 33 + jj];
            g_h[base + i]   = v;
            gflat[base + i] = v * g_dinv[gn];
        }
    }
}

// ---------------- vectorized edge gather: 8 lanes x float4, 4 edges / iter ----------------
__device__ __forceinline__ float4 gather_row(const float4* __restrict__ in4,
                                             const int* __restrict__ cs, int cnt,
                                             int jj, int q) {
    float4 acc = make_float4(0.f, 0.f, 0.f, 0.f);
    int j = 0;
    for (; j + 8 <= cnt; j += 8) {
        int s0 = __ldg(cs + j + jj);
        int s1 = __ldg(cs + j + 4 + jj);
        float4 v0 = in4[s0 * 8 + q];
        float4 v1 = in4[s1 * 8 + q];
        acc.x += v0.x + v1.x; acc.y += v0.y + v1.y;
        acc.z += v0.z + v1.z; acc.w += v0.w + v1.w;
    }
    if (j + 4 <= cnt) {
        int s = __ldg(cs + j + jj);
        float4 v = in4[s * 8 + q];
        acc.x += v.x; acc.y += v.y; acc.z += v.z; acc.w += v.w;
        j += 4;
    }
    int rem = cnt - j;
    if (jj < rem) {
        int s = __ldg(cs + j + jj);
        float4 v = in4[s * 8 + q];
        acc.x += v.x; acc.y += v.y; acc.z += v.z; acc.w += v.w;
    }
    // reduce across jj groups (lanes q, q+8, q+16, q+24)
    acc.x += __shfl_xor_sync(0xffffffffu, acc.x, 8);
    acc.y += __shfl_xor_sync(0xffffffffu, acc.y, 8);
    acc.z += __shfl_xor_sync(0xffffffffu, acc.z, 8);
    acc.w += __shfl_xor_sync(0xffffffffu, acc.w, 8);
    acc.x += __shfl_xor_sync(0xffffffffu, acc.x, 16);
    acc.y += __shfl_xor_sync(0xffffffffu, acc.y, 16);
    acc.z += __shfl_xor_sync(0xffffffffu, acc.z, 16);
    acc.w += __shfl_xor_sync(0xffffffffu, acc.w, 16);
    return acc;
}

// ---------------- spmm1: y1 = S h (scaled), gb = dinv * y1 ----------------
__global__ void spmm1_kernel(int N) {
    int w = (blockIdx.x * blockDim.x + threadIdx.x) >> 5;
    if (w >= N) return;
    int lane = threadIdx.x & 31;
    int jj = lane >> 3, q = lane & 7;
    const int* cs = g_csrc + g_rowptr[w];
    int cnt = g_degi[w];
    float4 acc = gather_row(g_g4, cs, cnt, jj, q);
    if (lane < 8) {
        float dv = g_dinv[w];
        float4 s4 = make_float4(acc.x * dv, acc.y * dv, acc.z * dv, acc.w * dv);
        g_y14[w * 8 + q] = s4;
        g_gb4[w * 8 + q] = make_float4(s4.x * dv, s4.y * dv, s4.z * dv, s4.w * dv);
    }
}

// ---------------- fused: spmm2 (S^2 h) + filters + attention + classifier ----------------
__global__ void fused_final(const float* __restrict__ W2, const float* __restrict__ b2,
                            const float* __restrict__ Wc, const float* __restrict__ bc,
                            const float* __restrict__ wbern,
                            float* __restrict__ out, int N) {
    __shared__ __align__(16) float sW2[H * H];
    __shared__ float sb2[H];
    __shared__ float sWc[H * 2];
    __shared__ float sbc[2];
    __shared__ float scf[9];
    __shared__ float4 st4[8][8];       // native float4: guaranteed 16B alignment
    int tid = threadIdx.x;
    for (int i = tid; i < H * H; i += blockDim.x) sW2[i] = W2[i];
    if (tid < H) {
        sb2[tid] = b2[tid];
        sWc[tid * 2]     = Wc[tid * 2];
        sWc[tid * 2 + 1] = Wc[tid * 2 + 1];
    }
    if (tid < 2) sbc[tid] = bc[tid];
    if (tid < 3) {
        float w0 = fmaxf(wbern[tid * 3 + 0], 0.f);
        float w1 = fmaxf(wbern[tid * 3 + 1], 0.f);
        float w2 = fmaxf(wbern[tid * 3 + 2], 0.f);
        scf[tid * 3 + 0] = 0.25f * (w0 + 2.f * w1 + w2);
        scf[tid * 3 + 1] = 0.50f * (w0 - w2);
        scf[tid * 3 + 2] = 0.25f * (w0 - 2.f * w1 + w2);
    }
    __syncthreads();

    int warp = tid >> 5, lane = tid & 31;
    int n = blockIdx.x * 8 + warp;
    if (n >= N) return;
    int jj = lane >> 3, q = lane & 7;

    // spmm2 part: acc = raw sum of gb rows
    const int* cs = g_csrc + g_rowptr[n];
    int cnt = g_degi[n];
    float4 acc = gather_row(g_gb4, cs, cnt, jj, q);

    float dv = g_dinv[n];
    if (lane < 8) {
        st4[warp][q] = make_float4(acc.x * dv, acc.y * dv, acc.z * dv, acc.w * dv);
    }
    __syncwarp();

    float a2 = ((const float*)st4[warp])[lane];      // S^2 h
    float hn = g_h[n * H + lane];                    // h
    float a1 = ((const float*)g_y14)[n * H + lane];  // S h

    float f0 = scf[0] * hn + scf[1] * a1 + scf[2] * a2;
    float f1 = scf[3] * hn + scf[4] * a1 + scf[5] * a2;
    float f2 = scf[6] * hn + scf[7] * a1 + scf[8] * a2;

    // 3 raw GEMVs (projections of h, Sh, S^2h); f_l projections are linear combos
    float Gh = 0.f, G1 = 0.f, G2 = 0.f;
    #pragma unroll
    for (int k = 0; k < 32; k++) {
        float w = sW2[k * H + lane];
        Gh = fmaf(__shfl_sync(0xffffffffu, hn, k), w, Gh);
        G1 = fmaf(__shfl_sync(0xffffffffu, a1, k), w, G1);
        G2 = fmaf(__shfl_sync(0xffffffffu, a2, k), w, G2);
    }
    float bb = sb2[lane];
    float px = tanhf(Gh + bb);
    float p0 = tanhf(scf[0] * Gh + scf[1] * G1 + scf[2] * G2 + bb);
    float p1 = tanhf(scf[3] * Gh + scf[4] * G1 + scf[5] * G2 + bb);
    float p2 = tanhf(scf[6] * Gh + scf[7] * G1 + scf[8] * G2 + bb);

    float l0 = p0 * px, l1 = p1 * px, l2 = p2 * px;
    #pragma unroll
    for (int o = 16; o; o >>= 1) {
        l0 += __shfl_xor_sync(0xffffffffu, l0, o);
        l1 += __shfl_xor_sync(0xffffffffu, l1, o);
        l2 += __shfl_xor_sync(0xffffffffu, l2, o);
    }
    float m  = fmaxf(l0, fmaxf(l1, l2));
    float e0 = expf(l0 - m), e1 = expf(l1 - m), e2 = expf(l2 - m);
    float inv = 1.f / (e0 + e1 + e2);
    float res = (e0 * f0 + e1 * f1 + e2 * f2) * inv;

    float o0 = res * sWc[lane * 2];
    float o1 = res * sWc[lane * 2 + 1];
    #pragma unroll
    for (int o = 16; o; o >>= 1) {
        o0 += __shfl_xor_sync(0xffffffffu, o0, o);
        o1 += __shfl_xor_sync(0xffffffffu, o1, o);
    }
    if (lane == 0) {
        out[n * 2]     = o0 + sbc[0];
        out[n * 2 + 1] = o1 + sbc[1];
        g_degi[n] = 0;   // restore zero invariant for next call
    }
}

// ---------------- launcher ----------------
extern "C" void kernel_launch(void* const* d_in, const int* in_sizes, int n_in,
                              void* d_out, int out_size) {
    const float* feature = (const float*)d_in[0];
    const float* W1      = (const float*)d_in[1];
    const float* b1      = (const float*)d_in[2];
    const float* W2      = (const float*)d_in[3];
    const float* b2      = (const float*)d_in[4];
    const float* Wc      = (const float*)d_in[5];
    const float* bc      = (const float*)d_in[6];
    const float* wbern   = (const float*)d_in[7];
    const int*   src     = (const int*)d_in[8];
    const int*   dst     = (const int*)d_in[9];

    int N = in_sizes[0] / FIN;
    int E = in_sizes[8];
    float* out = (float*)d_out;

    int nblk = (N + 511) / 512;

    deg_kernel<<<(E + 255) / 256, 256>>>(dst, E);
    scan1<<<nblk, 512>>>(N);
    scan2<<<1, 512>>>(nblk);
    scan3<<<nblk, 512>>>(N);
    scatter_kernel<<<(E + 255) / 256, 256>>>(src, dst, E);
    mlp_kernel<<<(N + 127) / 128, 128>>>(feature, W1, b1, W2, b2, N);
    spmm1_kernel<<<(N + 7) / 8, 256>>>(N);
    fused_final<<<(N + 7) / 8, 256>>>(W2, b2, Wc, bc, wbern, out, N);
}